// round 6
// baseline (speedup 1.0000x reference)
#include <cuda_runtime.h>
#include <cuda_bf16.h>

// Problem constants (shapes fixed by dataset; grids still computed from in_sizes)
#define NN   100000
#define EE   1600000
#define DIN  128
#define DH   128
#define DOUT 16

// Scratch (device globals are the sanctioned scratch mechanism — no allocations)
__device__ float g_h1[(size_t)NN * DH];    // X @ W1
__device__ float g_a1[(size_t)NN * DH];    // aggregated layer-1 (pre bias/relu)
__device__ float g_h2[(size_t)NN * DOUT];  // relu(a1+b1) @ W2
__device__ float g_dinv[NN];
__device__ int   g_deg[NN];

// ---------------------------------------------------------------------------
// Degree / normalization  (edge_index is int32! JAX default x64-disabled
// silently downgrades the reference's int64 to int32.)
// ---------------------------------------------------------------------------
__global__ void k_deg_init(int n) {
    int i = blockIdx.x * blockDim.x + threadIdx.x;
    if (i < n) g_deg[i] = 1;  // self-loop contributes 1 to every node
}

__global__ void k_deg_count(const int* __restrict__ ei, int E) {
    int e = blockIdx.x * blockDim.x + threadIdx.x;
    if (e < E) atomicAdd(&g_deg[ei[E + e]], 1);  // dst row
}

__global__ void k_dinv(int n) {
    int i = blockIdx.x * blockDim.x + threadIdx.x;
    if (i < n) g_dinv[i] = rsqrtf((float)g_deg[i]);  // deg >= 1 always
}

// ---------------------------------------------------------------------------
// GEMM1: g_h1[N,128] = X[N,128] @ W1[128,128]   (fp32 SIMT, smem-tiled)
// Block: 256 threads, 32 rows. Thread (cg=tid&31, rg=tid>>5) computes
// 4 rows (rg+8*ri) x 4 cols (cg*4..+3). K split in two 64-halves.
// ---------------------------------------------------------------------------
__global__ __launch_bounds__(256) void k_gemm1(const float* __restrict__ X,
                                               const float* __restrict__ W,
                                               int n) {
    __shared__ float Ws[64 * 128];  // 32KB: Ws[kk*128 + c]
    __shared__ float Xs[32 * 64];   // 8KB:  Xs[r*64 + kk]
    int tid  = threadIdx.x;
    int cg   = tid & 31;
    int rg   = tid >> 5;
    int row0 = blockIdx.x * 32;

    float4 acc[4];
#pragma unroll
    for (int ri = 0; ri < 4; ri++) acc[ri] = make_float4(0.f, 0.f, 0.f, 0.f);

    for (int kt = 0; kt < 2; kt++) {
        __syncthreads();
        const float4* W4  = (const float4*)W;
        float4*       Ws4 = (float4*)Ws;
#pragma unroll
        for (int i = 0; i < 8; i++)
            Ws4[tid + i * 256] = W4[kt * 2048 + tid + i * 256];
        const float4* X4  = (const float4*)X;
        float4*       Xs4 = (float4*)Xs;
#pragma unroll
        for (int i = 0; i < 2; i++) {
            int q = tid + i * 256;
            int r = q >> 4, kq = q & 15;
            int row = row0 + r;
            Xs4[r * 16 + kq] = (row < n) ? X4[(size_t)row * 32 + kt * 16 + kq]
                                         : make_float4(0.f, 0.f, 0.f, 0.f);
        }
        __syncthreads();

#pragma unroll 4
        for (int kk = 0; kk < 64; kk++) {
            float4 w = *(const float4*)&Ws[kk * 128 + cg * 4];
#pragma unroll
            for (int ri = 0; ri < 4; ri++) {
                float xv = Xs[(rg + 8 * ri) * 64 + kk];  // warp-broadcast
                acc[ri].x = fmaf(xv, w.x, acc[ri].x);
                acc[ri].y = fmaf(xv, w.y, acc[ri].y);
                acc[ri].z = fmaf(xv, w.z, acc[ri].z);
                acc[ri].w = fmaf(xv, w.w, acc[ri].w);
            }
        }
    }

#pragma unroll
    for (int ri = 0; ri < 4; ri++) {
        int row = row0 + rg + 8 * ri;
        if (row < n)
            *(float4*)&g_h1[(size_t)row * 128 + cg * 4] = acc[ri];
    }
}

// ---------------------------------------------------------------------------
// Layer-1 aggregation.
// k_self1: self-loop contribution via plain stores (initializes g_a1)
// k_edge1: warp per edge; each lane loads float4, does 4 scalar atomicAdds.
// ---------------------------------------------------------------------------
__global__ void k_self1(int n) {
    int idx = blockIdx.x * blockDim.x + threadIdx.x;  // float4 granularity
    if (idx < n * 32) {
        int i   = idx >> 5;
        float s = g_dinv[i];
        s *= s;
        float4 v = ((const float4*)g_h1)[idx];
        v.x *= s; v.y *= s; v.z *= s; v.w *= s;
        ((float4*)g_a1)[idx] = v;
    }
}

__global__ __launch_bounds__(256) void k_edge1(const int* __restrict__ ei, int E) {
    int e    = blockIdx.x * 8 + (threadIdx.x >> 5);
    int lane = threadIdx.x & 31;
    if (e >= E) return;
    int s = __ldg(&ei[e]);
    int t = __ldg(&ei[E + e]);
    float w = g_dinv[s] * g_dinv[t];
    float4 v = ((const float4*)g_h1)[(size_t)s * 32 + lane];  // 512B/warp, contiguous
    float* dst = g_a1 + (size_t)t * 128 + lane * 4;
    atomicAdd(dst + 0, v.x * w);
    atomicAdd(dst + 1, v.y * w);
    atomicAdd(dst + 2, v.z * w);
    atomicAdd(dst + 3, v.w * w);
}

// ---------------------------------------------------------------------------
// GEMM2: g_h2[N,16] = relu(g_a1 + b1)[N,128] @ W2[128,16]
// bias + relu fused into the shared-memory staging load.
// ---------------------------------------------------------------------------
__global__ __launch_bounds__(256) void k_gemm2(const float* __restrict__ b1,
                                               const float* __restrict__ W2,
                                               int n) {
    __shared__ float As[64 * 132];   // ~33KB, stride 132 avoids bank conflicts
    __shared__ float W2s[128 * 16];  // 8KB: W2s[k*16 + c]
    __shared__ float b1s[128];
    int tid  = threadIdx.x;
    int row0 = blockIdx.x * 64;

    if (tid < 128) b1s[tid] = b1[tid];
#pragma unroll
    for (int i = 0; i < 8; i++) W2s[tid + i * 256] = W2[tid + i * 256];
    __syncthreads();

#pragma unroll
    for (int i = 0; i < 32; i++) {
        int q = tid + i * 256;
        int r = q >> 7, k = q & 127;
        int row = row0 + r;
        float v = 0.f;
        if (row < n) v = fmaxf(g_a1[(size_t)row * 128 + k] + b1s[k], 0.f);
        As[r * 132 + k] = v;
    }
    __syncthreads();

    int cgrp = tid & 3;
    int r    = tid >> 2;
    float4 acc = make_float4(0.f, 0.f, 0.f, 0.f);
#pragma unroll 8
    for (int k = 0; k < 128; k++) {
        float  xv = As[r * 132 + k];
        float4 w  = *(const float4*)&W2s[k * 16 + cgrp * 4];
        acc.x = fmaf(xv, w.x, acc.x);
        acc.y = fmaf(xv, w.y, acc.y);
        acc.z = fmaf(xv, w.z, acc.z);
        acc.w = fmaf(xv, w.w, acc.w);
    }
    int row = row0 + r;
    if (row < n)
        *(float4*)&g_h2[(size_t)row * 16 + cgrp * 4] = acc;
}

// ---------------------------------------------------------------------------
// Layer-2 aggregation into d_out (self-loop + b2 init, then edge atomics)
// ---------------------------------------------------------------------------
__global__ void k_self2(const float* __restrict__ b2, float* __restrict__ out, int n) {
    int idx = blockIdx.x * blockDim.x + threadIdx.x;  // n*16 elements
    if (idx < n * 16) {
        int i = idx >> 4, d = idx & 15;
        float s = g_dinv[i];
        out[idx] = g_h2[idx] * s * s + b2[d];
    }
}

__global__ __launch_bounds__(256) void k_edge2(const int* __restrict__ ei,
                                               float* __restrict__ out, int E) {
    int gid = blockIdx.x * 256 + threadIdx.x;
    int e = gid >> 2, j = gid & 3;   // 4 threads per edge, 16 floats
    if (e >= E) return;
    int s = __ldg(&ei[e]);
    int t = __ldg(&ei[E + e]);
    float w = g_dinv[s] * g_dinv[t];
    float4 v = ((const float4*)g_h2)[(size_t)s * 4 + j];
    float* dst = out + (size_t)t * 16 + j * 4;
    atomicAdd(dst + 0, v.x * w);
    atomicAdd(dst + 1, v.y * w);
    atomicAdd(dst + 2, v.z * w);
    atomicAdd(dst + 3, v.w * w);
}

// ---------------------------------------------------------------------------
extern "C" void kernel_launch(void* const* d_in, const int* in_sizes, int n_in,
                              void* d_out, int out_size) {
    const float* x   = (const float*)d_in[0];
    const int*   ei  = (const int*)d_in[1];   // int32 [2, E] (JAX x64 disabled)
    const float* W1  = (const float*)d_in[2];
    const float* b1  = (const float*)d_in[3];
    const float* W2  = (const float*)d_in[4];
    const float* b2  = (const float*)d_in[5];
    float*       out = (float*)d_out;

    int n = in_sizes[0] / DIN;   // 100000
    int E = in_sizes[1] / 2;     // 1600000

    // normalization
    k_deg_init <<<(n + 255) / 256, 256>>>(n);
    k_deg_count<<<(E + 255) / 256, 256>>>(ei, E);
    k_dinv     <<<(n + 255) / 256, 256>>>(n);

    // layer 1
    k_gemm1<<<(n + 31) / 32, 256>>>(x, W1, n);
    k_self1<<<(n * 32 + 255) / 256, 256>>>(n);
    k_edge1<<<(E + 7) / 8, 256>>>(ei, E);

    // layer 2
    k_gemm2<<<(n + 63) / 64, 256>>>(b1, W2, n);
    k_self2<<<(n * 16 + 255) / 256, 256>>>(b2, out, n);
    k_edge2<<<(E * 4 + 255) / 256, 256>>>(ei, out, E);
}

// round 10
// speedup vs baseline: 2.7053x; 2.7053x over previous
#include <cuda_runtime.h>
#include <cuda_bf16.h>

// Problem constants (shapes fixed by dataset; grids still computed from in_sizes)
#define NN   100000
#define EE   1600000
#define DIN  128
#define DH   128
#define DOUT 16
#define SCAN_BLK 1024   // nodes per scan block

// Scratch (device globals — the sanctioned scratch mechanism)
__device__ float g_h1[(size_t)NN * DH];    // dinv * (X @ W1)
__device__ float g_a1[(size_t)NN * DH];    // aggregated layer-1 (pre bias/relu)
__device__ float g_h2[(size_t)NN * DOUT];  // dinv * (relu(a1+b1) @ W2)
__device__ float g_dinv[NN];
__device__ int   g_deg[NN];                // edge in-degree (no self-loop)
__device__ int   g_rowstart[NN + 1];
__device__ int   g_cursor[NN];
__device__ int   g_csr[EE];                // src indices bucketed by dst
__device__ int   g_bsum[128];              // per-scan-block sums

// ---------------------------------------------------------------------------
// Degree / normalization  (edge_index is int32: JAX x64-disabled)
// ---------------------------------------------------------------------------
__global__ void k_deg_zero(int n) {
    int i = blockIdx.x * blockDim.x + threadIdx.x;
    if (i < n) g_deg[i] = 0;
}

__global__ void k_deg_count(const int* __restrict__ ei, int E) {
    int e = blockIdx.x * blockDim.x + threadIdx.x;
    if (e < E) atomicAdd(&g_deg[ei[E + e]], 1);  // dst row
}

__global__ void k_dinv(int n) {
    int i = blockIdx.x * blockDim.x + threadIdx.x;
    if (i < n) g_dinv[i] = rsqrtf((float)(g_deg[i] + 1));  // +1 self-loop
}

// ---------------------------------------------------------------------------
// Exclusive scan of g_deg -> g_rowstart (3 kernels), cursor initialized too.
// ---------------------------------------------------------------------------
__global__ __launch_bounds__(256) void k_scan_reduce(int n) {
    __shared__ int wsum[8];
    int b    = blockIdx.x;
    int base = b * SCAN_BLK + threadIdx.x * 4;
    int t = 0;
#pragma unroll
    for (int i = 0; i < 4; i++) {
        int idx = base + i;
        if (idx < n) t += g_deg[idx];
    }
#pragma unroll
    for (int o = 16; o > 0; o >>= 1) t += __shfl_down_sync(~0u, t, o);
    int lane = threadIdx.x & 31, wid = threadIdx.x >> 5;
    if (lane == 0) wsum[wid] = t;
    __syncthreads();
    if (threadIdx.x == 0) {
        int s = 0;
#pragma unroll
        for (int w = 0; w < 8; w++) s += wsum[w];
        g_bsum[b] = s;
    }
}

__global__ void k_scan_top(int nblocks) {
    if (threadIdx.x == 0 && blockIdx.x == 0) {
        int run = 0;
        for (int i = 0; i < nblocks; i++) {
            int t = g_bsum[i];
            g_bsum[i] = run;
            run += t;
        }
    }
}

__global__ __launch_bounds__(256) void k_scan_local(int n, int E) {
    __shared__ int wsum[8];
    int b    = blockIdx.x;
    int base = b * SCAN_BLK + threadIdx.x * 4;
    int lane = threadIdx.x & 31, wid = threadIdx.x >> 5;
    int c[4];
    int t = 0;
#pragma unroll
    for (int i = 0; i < 4; i++) {
        int idx = base + i;
        c[i] = (idx < n) ? g_deg[idx] : 0;
        t += c[i];
    }
    int incl = t;
#pragma unroll
    for (int o = 1; o < 32; o <<= 1) {
        int v = __shfl_up_sync(~0u, incl, o);
        if (lane >= o) incl += v;
    }
    if (lane == 31) wsum[wid] = incl;
    __syncthreads();
    if (threadIdx.x == 0) {
        int run = 0;
#pragma unroll
        for (int w = 0; w < 8; w++) { int v = wsum[w]; wsum[w] = run; run += v; }
    }
    __syncthreads();
    int p = g_bsum[b] + wsum[wid] + incl - t;  // exclusive prefix (thread's 1st node)
#pragma unroll
    for (int i = 0; i < 4; i++) {
        int idx = base + i;
        if (idx < n) { g_rowstart[idx] = p; g_cursor[idx] = p; }
        p += c[i];
    }
    if (b == 0 && threadIdx.x == 0) g_rowstart[n] = E;
}

__global__ void k_fill(const int* __restrict__ ei, int E) {
    int e = blockIdx.x * blockDim.x + threadIdx.x;
    if (e < E) {
        int s = ei[e], t = ei[E + e];
        int pos = atomicAdd(&g_cursor[t], 1);
        g_csr[pos] = s;
    }
}

// ---------------------------------------------------------------------------
// GEMM1: g_h1[N,128] = dinv[row] * (X[N,128] @ W1[128,128])
// ---------------------------------------------------------------------------
__global__ __launch_bounds__(256) void k_gemm1(const float* __restrict__ X,
                                               const float* __restrict__ W,
                                               int n) {
    __shared__ float Ws[64 * 128];
    __shared__ float Xs[32 * 64];
    int tid  = threadIdx.x;
    int cg   = tid & 31;
    int rg   = tid >> 5;
    int row0 = blockIdx.x * 32;

    float4 acc[4];
#pragma unroll
    for (int ri = 0; ri < 4; ri++) acc[ri] = make_float4(0.f, 0.f, 0.f, 0.f);

    for (int kt = 0; kt < 2; kt++) {
        __syncthreads();
        const float4* W4  = (const float4*)W;
        float4*       Ws4 = (float4*)Ws;
#pragma unroll
        for (int i = 0; i < 8; i++)
            Ws4[tid + i * 256] = W4[kt * 2048 + tid + i * 256];
        const float4* X4  = (const float4*)X;
        float4*       Xs4 = (float4*)Xs;
#pragma unroll
        for (int i = 0; i < 2; i++) {
            int q = tid + i * 256;
            int r = q >> 4, kq = q & 15;
            int row = row0 + r;
            Xs4[r * 16 + kq] = (row < n) ? X4[(size_t)row * 32 + kt * 16 + kq]
                                         : make_float4(0.f, 0.f, 0.f, 0.f);
        }
        __syncthreads();

#pragma unroll 4
        for (int kk = 0; kk < 64; kk++) {
            float4 w = *(const float4*)&Ws[kk * 128 + cg * 4];
#pragma unroll
            for (int ri = 0; ri < 4; ri++) {
                float xv = Xs[(rg + 8 * ri) * 64 + kk];
                acc[ri].x = fmaf(xv, w.x, acc[ri].x);
                acc[ri].y = fmaf(xv, w.y, acc[ri].y);
                acc[ri].z = fmaf(xv, w.z, acc[ri].z);
                acc[ri].w = fmaf(xv, w.w, acc[ri].w);
            }
        }
    }

#pragma unroll
    for (int ri = 0; ri < 4; ri++) {
        int row = row0 + rg + 8 * ri;
        if (row < n) {
            float d = g_dinv[row];
            acc[ri].x *= d; acc[ri].y *= d; acc[ri].z *= d; acc[ri].w *= d;
            *(float4*)&g_h1[(size_t)row * 128 + cg * 4] = acc[ri];
        }
    }
}

// ---------------------------------------------------------------------------
// Gather layer 1: warp per node; lane owns one float4 of the 128-float row.
// a1[t] = dinv[t] * (h1s[t] + sum_{s in N(t)} h1s[s])     (h1s already dinv-scaled)
// ---------------------------------------------------------------------------
__global__ __launch_bounds__(256) void k_gather1(int n) {
    int node = blockIdx.x * 8 + (threadIdx.x >> 5);
    int lane = threadIdx.x & 31;
    if (node >= n) return;
    int beg = g_rowstart[node];
    int end = g_rowstart[node + 1];
    const float4* h4 = (const float4*)g_h1;

    float4 acc = h4[(size_t)node * 32 + lane];  // self-loop term
    int j = beg;
    for (; j + 1 < end; j += 2) {               // 2-way unroll for MLP
        int s0 = g_csr[j];
        int s1 = g_csr[j + 1];
        float4 v0 = h4[(size_t)s0 * 32 + lane];
        float4 v1 = h4[(size_t)s1 * 32 + lane];
        acc.x += v0.x + v1.x;
        acc.y += v0.y + v1.y;
        acc.z += v0.z + v1.z;
        acc.w += v0.w + v1.w;
    }
    if (j < end) {
        int s0 = g_csr[j];
        float4 v0 = h4[(size_t)s0 * 32 + lane];
        acc.x += v0.x; acc.y += v0.y; acc.z += v0.z; acc.w += v0.w;
    }
    float d = g_dinv[node];
    acc.x *= d; acc.y *= d; acc.z *= d; acc.w *= d;
    ((float4*)g_a1)[(size_t)node * 32 + lane] = acc;
}

// ---------------------------------------------------------------------------
// GEMM2: g_h2[N,16] = dinv[row] * (relu(g_a1 + b1)[N,128] @ W2[128,16])
// ---------------------------------------------------------------------------
__global__ __launch_bounds__(256) void k_gemm2(const float* __restrict__ b1,
                                               const float* __restrict__ W2,
                                               int n) {
    __shared__ float As[64 * 132];
    __shared__ float W2s[128 * 16];
    __shared__ float b1s[128];
    int tid  = threadIdx.x;
    int row0 = blockIdx.x * 64;

    if (tid < 128) b1s[tid] = b1[tid];
#pragma unroll
    for (int i = 0; i < 8; i++) W2s[tid + i * 256] = W2[tid + i * 256];
    __syncthreads();

#pragma unroll
    for (int i = 0; i < 32; i++) {
        int q = tid + i * 256;
        int r = q >> 7, k = q & 127;
        int row = row0 + r;
        float v = 0.f;
        if (row < n) v = fmaxf(g_a1[(size_t)row * 128 + k] + b1s[k], 0.f);
        As[r * 132 + k] = v;
    }
    __syncthreads();

    int cgrp = tid & 3;
    int r    = tid >> 2;
    float4 acc = make_float4(0.f, 0.f, 0.f, 0.f);
#pragma unroll 8
    for (int k = 0; k < 128; k++) {
        float  xv = As[r * 132 + k];
        float4 w  = *(const float4*)&W2s[k * 16 + cgrp * 4];
        acc.x = fmaf(xv, w.x, acc.x);
        acc.y = fmaf(xv, w.y, acc.y);
        acc.z = fmaf(xv, w.z, acc.z);
        acc.w = fmaf(xv, w.w, acc.w);
    }
    int row = row0 + r;
    if (row < n) {
        float d = g_dinv[row];
        acc.x *= d; acc.y *= d; acc.z *= d; acc.w *= d;
        *(float4*)&g_h2[(size_t)row * 16 + cgrp * 4] = acc;
    }
}

// ---------------------------------------------------------------------------
// Gather layer 2: 4 threads per node (each one float4 of 16-float row),
// writes d_out directly:  out[t] = dinv[t]*(h2s[t] + sum h2s[s]) + b2
// ---------------------------------------------------------------------------
__global__ __launch_bounds__(256) void k_gather2(const float* __restrict__ b2,
                                                 float* __restrict__ out, int n) {
    int gid  = blockIdx.x * 256 + threadIdx.x;
    int node = gid >> 2;
    int j4   = gid & 3;
    if (node >= n) return;
    int beg = g_rowstart[node];
    int end = g_rowstart[node + 1];
    const float4* h4 = (const float4*)g_h2;

    float4 acc = h4[(size_t)node * 4 + j4];     // self-loop term
    int j = beg;
    for (; j + 1 < end; j += 2) {
        int s0 = g_csr[j];
        int s1 = g_csr[j + 1];
        float4 v0 = h4[(size_t)s0 * 4 + j4];
        float4 v1 = h4[(size_t)s1 * 4 + j4];
        acc.x += v0.x + v1.x;
        acc.y += v0.y + v1.y;
        acc.z += v0.z + v1.z;
        acc.w += v0.w + v1.w;
    }
    if (j < end) {
        int s0 = g_csr[j];
        float4 v0 = h4[(size_t)s0 * 4 + j4];
        acc.x += v0.x; acc.y += v0.y; acc.z += v0.z; acc.w += v0.w;
    }
    float  d  = g_dinv[node];
    float4 bb = ((const float4*)b2)[j4];
    acc.x = fmaf(acc.x, d, bb.x);
    acc.y = fmaf(acc.y, d, bb.y);
    acc.z = fmaf(acc.z, d, bb.z);
    acc.w = fmaf(acc.w, d, bb.w);
    ((float4*)out)[(size_t)node * 4 + j4] = acc;
}

// ---------------------------------------------------------------------------
extern "C" void kernel_launch(void* const* d_in, const int* in_sizes, int n_in,
                              void* d_out, int out_size) {
    const float* x   = (const float*)d_in[0];
    const int*   ei  = (const int*)d_in[1];   // int32 [2, E]
    const float* W1  = (const float*)d_in[2];
    const float* b1  = (const float*)d_in[3];
    const float* W2  = (const float*)d_in[4];
    const float* b2  = (const float*)d_in[5];
    float*       out = (float*)d_out;

    int n = in_sizes[0] / DIN;   // 100000
    int E = in_sizes[1] / 2;     // 1600000
    int nblocks = (n + SCAN_BLK - 1) / SCAN_BLK;  // 98

    // degree + CSR build
    k_deg_zero   <<<(n + 255) / 256, 256>>>(n);
    k_deg_count  <<<(E + 255) / 256, 256>>>(ei, E);
    k_scan_reduce<<<nblocks, 256>>>(n);
    k_scan_top   <<<1, 32>>>(nblocks);
    k_scan_local <<<nblocks, 256>>>(n, E);
    k_dinv       <<<(n + 255) / 256, 256>>>(n);
    k_fill       <<<(E + 255) / 256, 256>>>(ei, E);

    // layer 1
    k_gemm1  <<<(n + 31) / 32, 256>>>(x, W1, n);
    k_gather1<<<(n + 7) / 8, 256>>>(n);

    // layer 2
    k_gemm2  <<<(n + 63) / 64, 256>>>(b1, W2, n);
    k_gather2<<<(n * 4 + 255) / 256, 256>>>(b2, out, n);
}

// round 11
// speedup vs baseline: 3.9184x; 1.4484x over previous
#include <cuda_runtime.h>
#include <cuda_bf16.h>

#define NN   100000
#define EE   1600000
#define DIN  128
#define DH   128
#define DOUT 16
#define SCAN_BLK 1024

// Scratch
__device__ float g_h1[(size_t)NN * DH];
__device__ float g_a1[(size_t)NN * DH];
__device__ float g_h2[(size_t)NN * DOUT];
__device__ float g_dinv[NN];
__device__ int   g_deg[NN];
__device__ int   g_rowstart[NN + 1];
__device__ int   g_cursor[NN];
__device__ int   g_csr[EE];
__device__ int   g_bsum[128];

// ---------------------------------------------------------------------------
// Degree / CSR build
// ---------------------------------------------------------------------------
__global__ void k_deg_zero(int n) {
    int i = blockIdx.x * blockDim.x + threadIdx.x;
    if (i < n) g_deg[i] = 0;
}

__global__ void k_deg_count(const int* __restrict__ ei, int E) {
    int e = blockIdx.x * blockDim.x + threadIdx.x;
    if (e < E) atomicAdd(&g_deg[ei[E + e]], 1);
}

__global__ __launch_bounds__(256) void k_scan_reduce(int n) {
    __shared__ int wsum[8];
    int b    = blockIdx.x;
    int base = b * SCAN_BLK + threadIdx.x * 4;
    int t = 0;
#pragma unroll
    for (int i = 0; i < 4; i++) {
        int idx = base + i;
        if (idx < n) t += g_deg[idx];
    }
#pragma unroll
    for (int o = 16; o > 0; o >>= 1) t += __shfl_down_sync(~0u, t, o);
    int lane = threadIdx.x & 31, wid = threadIdx.x >> 5;
    if (lane == 0) wsum[wid] = t;
    __syncthreads();
    if (threadIdx.x == 0) {
        int s = 0;
#pragma unroll
        for (int w = 0; w < 8; w++) s += wsum[w];
        g_bsum[b] = s;
    }
}

// Parallel exclusive scan of g_bsum (nblocks <= 128), one block of 128 threads.
__global__ void k_scan_top(int nblocks) {
    __shared__ int ws[4];
    int tid  = threadIdx.x;
    int lane = tid & 31, wid = tid >> 5;
    int v    = (tid < nblocks) ? g_bsum[tid] : 0;
    int incl = v;
#pragma unroll
    for (int o = 1; o < 32; o <<= 1) {
        int t = __shfl_up_sync(~0u, incl, o);
        if (lane >= o) incl += t;
    }
    if (lane == 31) ws[wid] = incl;
    __syncthreads();
    if (tid == 0) {
        int run = 0;
#pragma unroll
        for (int w = 0; w < 4; w++) { int t = ws[w]; ws[w] = run; run += t; }
    }
    __syncthreads();
    int excl = ws[wid] + incl - v;
    if (tid < nblocks) g_bsum[tid] = excl;
}

// Local scan + rowstart/cursor init + dinv (fused)
__global__ __launch_bounds__(256) void k_scan_local(int n, int E) {
    __shared__ int wsum[8];
    int b    = blockIdx.x;
    int base = b * SCAN_BLK + threadIdx.x * 4;
    int lane = threadIdx.x & 31, wid = threadIdx.x >> 5;
    int c[4];
    int t = 0;
#pragma unroll
    for (int i = 0; i < 4; i++) {
        int idx = base + i;
        c[i] = (idx < n) ? g_deg[idx] : 0;
        t += c[i];
    }
    int incl = t;
#pragma unroll
    for (int o = 1; o < 32; o <<= 1) {
        int v = __shfl_up_sync(~0u, incl, o);
        if (lane >= o) incl += v;
    }
    if (lane == 31) wsum[wid] = incl;
    __syncthreads();
    if (threadIdx.x == 0) {
        int run = 0;
#pragma unroll
        for (int w = 0; w < 8; w++) { int v = wsum[w]; wsum[w] = run; run += v; }
    }
    __syncthreads();
    int p = g_bsum[b] + wsum[wid] + incl - t;
#pragma unroll
    for (int i = 0; i < 4; i++) {
        int idx = base + i;
        if (idx < n) {
            g_rowstart[idx] = p;
            g_cursor[idx]   = p;
            g_dinv[idx]     = rsqrtf((float)(c[i] + 1));  // +1 self-loop
        }
        p += c[i];
    }
    if (b == 0 && threadIdx.x == 0) g_rowstart[n] = E;
}

__global__ void k_fill(const int* __restrict__ ei, int E) {
    int e = blockIdx.x * blockDim.x + threadIdx.x;
    if (e < E) {
        int s = ei[e], t = ei[E + e];
        int pos = atomicAdd(&g_cursor[t], 1);
        g_csr[pos] = s;
    }
}

// ---------------------------------------------------------------------------
// GEMM1 (tf32 tensor cores): g_h1[N,128] = dinv[row] * (X @ W1)
// Block: 256 threads, tile 128 rows x 128 cols, K chunked by 32.
// Warp grid 4x2: warp = 32 rows x 64 cols = 2 (m16) x 8 (n8) mma tiles.
// mma.sync.aligned.m16n8k8.row.col.f32.tf32.tf32.f32
// ---------------------------------------------------------------------------
__device__ __forceinline__ unsigned f2tf32(float f) {
    unsigned u;
    asm("cvt.rna.tf32.f32 %0, %1;" : "=r"(u) : "f"(f));
    return u;
}

__global__ __launch_bounds__(256) void k_gemm1(const float* __restrict__ X,
                                               const float* __restrict__ W,
                                               int n) {
    __shared__ unsigned Xs[128 * 36];  // rows x 32k, stride 36 (conflict-free frags)
    __shared__ unsigned Ws[32 * 136];  // k x 128 cols, stride 136 (conflict-free frags)
    int tid  = threadIdx.x;
    int lane = tid & 31;
    int wid  = tid >> 5;
    int gid  = lane >> 2;   // 0..7
    int tig  = lane & 3;    // 0..3
    int wr   = wid & 3;     // warp row group (32 rows each)
    int wc   = wid >> 2;    // warp col group (64 cols each)
    int row0 = blockIdx.x * 128;

    float acc[2][8][4];
#pragma unroll
    for (int mt = 0; mt < 2; mt++)
#pragma unroll
        for (int nt = 0; nt < 8; nt++)
#pragma unroll
            for (int q = 0; q < 4; q++) acc[mt][nt][q] = 0.f;

    const float4* X4 = (const float4*)X;
    const float4* W4 = (const float4*)W;

    for (int kt = 0; kt < 4; kt++) {
        __syncthreads();
        // Stage X chunk: 128 rows x 32 k  (1024 float4, 4 per thread)
#pragma unroll
        for (int i = 0; i < 4; i++) {
            int q = tid + i * 256;
            int r = q >> 3, c4 = q & 7;
            int row = row0 + r;
            float4 v = (row < n) ? X4[(size_t)row * 32 + kt * 8 + c4]
                                 : make_float4(0.f, 0.f, 0.f, 0.f);
            unsigned* d = &Xs[r * 36 + c4 * 4];
            d[0] = f2tf32(v.x); d[1] = f2tf32(v.y);
            d[2] = f2tf32(v.z); d[3] = f2tf32(v.w);
        }
        // Stage W chunk: 32 k x 128 cols  (1024 float4, 4 per thread)
#pragma unroll
        for (int i = 0; i < 4; i++) {
            int q = tid + i * 256;
            int r = q >> 5, c4 = q & 31;
            float4 v = W4[(size_t)(kt * 32 + r) * 32 + c4];
            unsigned* d = &Ws[r * 136 + c4 * 4];
            d[0] = f2tf32(v.x); d[1] = f2tf32(v.y);
            d[2] = f2tf32(v.z); d[3] = f2tf32(v.w);
        }
        __syncthreads();

#pragma unroll
        for (int ks = 0; ks < 4; ks++) {
            int kk = ks * 8;
            // A fragments (2 m16 tiles)
            unsigned a[2][4];
#pragma unroll
            for (int mt = 0; mt < 2; mt++) {
                int rb = wr * 32 + mt * 16;
                a[mt][0] = Xs[(rb + gid) * 36 + kk + tig];
                a[mt][1] = Xs[(rb + gid + 8) * 36 + kk + tig];
                a[mt][2] = Xs[(rb + gid) * 36 + kk + tig + 4];
                a[mt][3] = Xs[(rb + gid + 8) * 36 + kk + tig + 4];
            }
            // B fragments (8 n8 tiles)
            unsigned b[8][2];
#pragma unroll
            for (int nt = 0; nt < 8; nt++) {
                int col = wc * 64 + nt * 8 + gid;
                b[nt][0] = Ws[(kk + tig) * 136 + col];
                b[nt][1] = Ws[(kk + tig + 4) * 136 + col];
            }
#pragma unroll
            for (int mt = 0; mt < 2; mt++)
#pragma unroll
                for (int nt = 0; nt < 8; nt++) {
                    float* c = acc[mt][nt];
                    asm volatile(
                        "mma.sync.aligned.m16n8k8.row.col.f32.tf32.tf32.f32 "
                        "{%0,%1,%2,%3}, {%4,%5,%6,%7}, {%8,%9}, {%0,%1,%2,%3};"
                        : "+f"(c[0]), "+f"(c[1]), "+f"(c[2]), "+f"(c[3])
                        : "r"(a[mt][0]), "r"(a[mt][1]), "r"(a[mt][2]), "r"(a[mt][3]),
                          "r"(b[nt][0]), "r"(b[nt][1]));
                }
        }
    }

    // Epilogue: scale by dinv, store float2 pairs
#pragma unroll
    for (int mt = 0; mt < 2; mt++) {
        int rA = row0 + wr * 32 + mt * 16 + gid;
        int rB = rA + 8;
        float dA = (rA < n) ? g_dinv[rA] : 0.f;
        float dB = (rB < n) ? g_dinv[rB] : 0.f;
#pragma unroll
        for (int nt = 0; nt < 8; nt++) {
            int col = wc * 64 + nt * 8 + 2 * tig;
            if (rA < n) {
                float2 v = make_float2(acc[mt][nt][0] * dA, acc[mt][nt][1] * dA);
                *(float2*)&g_h1[(size_t)rA * 128 + col] = v;
            }
            if (rB < n) {
                float2 v = make_float2(acc[mt][nt][2] * dB, acc[mt][nt][3] * dB);
                *(float2*)&g_h1[(size_t)rB * 128 + col] = v;
            }
        }
    }
}

// ---------------------------------------------------------------------------
// Gather layer 1: warp per node, lane = one float4 of the row. 4-way unroll.
// ---------------------------------------------------------------------------
__global__ __launch_bounds__(256) void k_gather1(int n) {
    int node = blockIdx.x * 8 + (threadIdx.x >> 5);
    int lane = threadIdx.x & 31;
    if (node >= n) return;
    int beg = g_rowstart[node];
    int end = g_rowstart[node + 1];
    const float4* h4 = (const float4*)g_h1;

    float4 acc = h4[(size_t)node * 32 + lane];  // self-loop
    int j = beg;
    for (; j + 3 < end; j += 4) {
        int s0 = g_csr[j], s1 = g_csr[j + 1], s2 = g_csr[j + 2], s3 = g_csr[j + 3];
        float4 v0 = h4[(size_t)s0 * 32 + lane];
        float4 v1 = h4[(size_t)s1 * 32 + lane];
        float4 v2 = h4[(size_t)s2 * 32 + lane];
        float4 v3 = h4[(size_t)s3 * 32 + lane];
        acc.x += (v0.x + v1.x) + (v2.x + v3.x);
        acc.y += (v0.y + v1.y) + (v2.y + v3.y);
        acc.z += (v0.z + v1.z) + (v2.z + v3.z);
        acc.w += (v0.w + v1.w) + (v2.w + v3.w);
    }
    for (; j < end; j++) {
        int s0 = g_csr[j];
        float4 v0 = h4[(size_t)s0 * 32 + lane];
        acc.x += v0.x; acc.y += v0.y; acc.z += v0.z; acc.w += v0.w;
    }
    float d = g_dinv[node];
    acc.x *= d; acc.y *= d; acc.z *= d; acc.w *= d;
    ((float4*)g_a1)[(size_t)node * 32 + lane] = acc;
}

// ---------------------------------------------------------------------------
// GEMM2: g_h2[N,16] = dinv * (relu(g_a1 + b1) @ W2)
// 256 threads, tile 256 rows; thread = 4 rows x 4 cols; K chunked by 32.
// ---------------------------------------------------------------------------
__global__ __launch_bounds__(256) void k_gemm2(const float* __restrict__ b1,
                                               const float* __restrict__ W2,
                                               int n) {
    __shared__ float As[256 * 33];   // 33KB, stride 33 conflict-free
    __shared__ float W2s[128 * 16];  // 8KB
    __shared__ float b1s[128];
    int tid  = threadIdx.x;
    int cgrp = tid & 3;
    int tg   = tid >> 2;             // 0..63 -> rows tg*4..+3
    int row0 = blockIdx.x * 256;

    if (tid < 128) b1s[tid] = b1[tid];
#pragma unroll
    for (int i = 0; i < 8; i++) W2s[tid + i * 256] = W2[tid + i * 256];

    float4 acc[4];
#pragma unroll
    for (int i = 0; i < 4; i++) acc[i] = make_float4(0.f, 0.f, 0.f, 0.f);

    for (int kc = 0; kc < 4; kc++) {
        __syncthreads();
        // Stage 256 rows x 32 k with bias+relu (2048 float4, 8 per thread)
#pragma unroll
        for (int i = 0; i < 8; i++) {
            int q = tid + i * 256;
            int r = q >> 3, c4 = q & 7;
            int row = row0 + r;
            float4 v = make_float4(0.f, 0.f, 0.f, 0.f);
            if (row < n) {
                float4 a = ((const float4*)g_a1)[(size_t)row * 32 + kc * 8 + c4];
                const float* bb = &b1s[kc * 32 + c4 * 4];
                v.x = fmaxf(a.x + bb[0], 0.f);
                v.y = fmaxf(a.y + bb[1], 0.f);
                v.z = fmaxf(a.z + bb[2], 0.f);
                v.w = fmaxf(a.w + bb[3], 0.f);
            }
            float* d = &As[r * 33 + c4 * 4];
            d[0] = v.x; d[1] = v.y; d[2] = v.z; d[3] = v.w;
        }
        __syncthreads();

#pragma unroll 8
        for (int kk = 0; kk < 32; kk++) {
            float4 w = *(const float4*)&W2s[(kc * 32 + kk) * 16 + cgrp * 4];
#pragma unroll
            for (int i = 0; i < 4; i++) {
                float xv = As[(tg * 4 + i) * 33 + kk];
                acc[i].x = fmaf(xv, w.x, acc[i].x);
                acc[i].y = fmaf(xv, w.y, acc[i].y);
                acc[i].z = fmaf(xv, w.z, acc[i].z);
                acc[i].w = fmaf(xv, w.w, acc[i].w);
            }
        }
    }

#pragma unroll
    for (int i = 0; i < 4; i++) {
        int row = row0 + tg * 4 + i;
        if (row < n) {
            float d = g_dinv[row];
            acc[i].x *= d; acc[i].y *= d; acc[i].z *= d; acc[i].w *= d;
            *(float4*)&g_h2[(size_t)row * 16 + cgrp * 4] = acc[i];
        }
    }
}

// ---------------------------------------------------------------------------
// Gather layer 2: 4 threads per node, writes d_out (+b2) directly.
// ---------------------------------------------------------------------------
__global__ __launch_bounds__(256) void k_gather2(const float* __restrict__ b2,
                                                 float* __restrict__ out, int n) {
    int gid  = blockIdx.x * 256 + threadIdx.x;
    int node = gid >> 2;
    int j4   = gid & 3;
    if (node >= n) return;
    int beg = g_rowstart[node];
    int end = g_rowstart[node + 1];
    const float4* h4 = (const float4*)g_h2;

    float4 acc = h4[(size_t)node * 4 + j4];
    int j = beg;
    for (; j + 1 < end; j += 2) {
        int s0 = g_csr[j], s1 = g_csr[j + 1];
        float4 v0 = h4[(size_t)s0 * 4 + j4];
        float4 v1 = h4[(size_t)s1 * 4 + j4];
        acc.x += v0.x + v1.x;
        acc.y += v0.y + v1.y;
        acc.z += v0.z + v1.z;
        acc.w += v0.w + v1.w;
    }
    if (j < end) {
        int s0 = g_csr[j];
        float4 v0 = h4[(size_t)s0 * 4 + j4];
        acc.x += v0.x; acc.y += v0.y; acc.z += v0.z; acc.w += v0.w;
    }
    float  d  = g_dinv[node];
    float4 bb = ((const float4*)b2)[j4];
    acc.x = fmaf(acc.x, d, bb.x);
    acc.y = fmaf(acc.y, d, bb.y);
    acc.z = fmaf(acc.z, d, bb.z);
    acc.w = fmaf(acc.w, d, bb.w);
    ((float4*)out)[(size_t)node * 4 + j4] = acc;
}

// ---------------------------------------------------------------------------
extern "C" void kernel_launch(void* const* d_in, const int* in_sizes, int n_in,
                              void* d_out, int out_size) {
    const float* x   = (const float*)d_in[0];
    const int*   ei  = (const int*)d_in[1];   // int32 [2, E]
    const float* W1  = (const float*)d_in[2];
    const float* b1  = (const float*)d_in[3];
    const float* W2  = (const float*)d_in[4];
    const float* b2  = (const float*)d_in[5];
    float*       out = (float*)d_out;

    int n = in_sizes[0] / DIN;   // 100000
    int E = in_sizes[1] / 2;     // 1600000
    int nblocks = (n + SCAN_BLK - 1) / SCAN_BLK;  // 98

    // degree + CSR build (dinv fused into scan_local)
    k_deg_zero   <<<(n + 255) / 256, 256>>>(n);
    k_deg_count  <<<(E + 255) / 256, 256>>>(ei, E);
    k_scan_reduce<<<nblocks, 256>>>(n);
    k_scan_top   <<<1, 128>>>(nblocks);
    k_scan_local <<<nblocks, 256>>>(n, E);
    k_fill       <<<(E + 255) / 256, 256>>>(ei, E);

    // layer 1
    k_gemm1  <<<(n + 127) / 128, 256>>>(x, W1, n);
    k_gather1<<<(n + 7) / 8, 256>>>(n);

    // layer 2
    k_gemm2  <<<(n + 255) / 256, 256>>>(b1, W2, n);
    k_gather2<<<(n * 4 + 255) / 256, 256>>>(b2, out, n);
}

// round 13
// speedup vs baseline: 4.3039x; 1.0984x over previous
#include <cuda_runtime.h>
#include <cuda_fp16.h>

#define NN   100000
#define EE   1600000
#define DIN  128
#define DH   128
#define DOUT 16
#define SCAN_BLK 1024

// Scratch
__device__ __half g_h1h[(size_t)NN * DH];    // fp16: dinv * (X @ W1)
__device__ float  g_a1[(size_t)NN * DH];     // fp32 aggregated layer-1
__device__ __half g_h2h[(size_t)NN * DOUT];  // fp16: dinv * (relu(a1+b1) @ W2)
__device__ float  g_dinv[NN];
__device__ int    g_deg[NN];
__device__ int    g_rowstart[NN + 1];
__device__ int    g_cursor[NN];
__device__ int    g_csr[EE];
__device__ int    g_bsum[128];

// ---------------------------------------------------------------------------
// Degree / CSR build
// ---------------------------------------------------------------------------
__global__ void k_deg_zero(int n) {
    int i = blockIdx.x * blockDim.x + threadIdx.x;
    if (i < n) g_deg[i] = 0;
}

__global__ void k_deg_count(const int* __restrict__ ei, int E) {
    int e2 = blockIdx.x * blockDim.x + threadIdx.x;   // 2 edges per thread
    int e  = e2 * 2;
    if (e + 1 < E) {
        int2 d = *(const int2*)&ei[E + e];
        atomicAdd(&g_deg[d.x], 1);
        atomicAdd(&g_deg[d.y], 1);
    } else if (e < E) {
        atomicAdd(&g_deg[ei[E + e]], 1);
    }
}

__global__ __launch_bounds__(256) void k_scan_reduce(int n) {
    __shared__ int wsum[8];
    int b    = blockIdx.x;
    int base = b * SCAN_BLK + threadIdx.x * 4;
    int t = 0;
#pragma unroll
    for (int i = 0; i < 4; i++) {
        int idx = base + i;
        if (idx < n) t += g_deg[idx];
    }
#pragma unroll
    for (int o = 16; o > 0; o >>= 1) t += __shfl_down_sync(~0u, t, o);
    int lane = threadIdx.x & 31, wid = threadIdx.x >> 5;
    if (lane == 0) wsum[wid] = t;
    __syncthreads();
    if (threadIdx.x == 0) {
        int s = 0;
#pragma unroll
        for (int w = 0; w < 8; w++) s += wsum[w];
        g_bsum[b] = s;
    }
}

__global__ void k_scan_top(int nblocks) {
    __shared__ int ws[4];
    int tid  = threadIdx.x;
    int lane = tid & 31, wid = tid >> 5;
    int v    = (tid < nblocks) ? g_bsum[tid] : 0;
    int incl = v;
#pragma unroll
    for (int o = 1; o < 32; o <<= 1) {
        int t = __shfl_up_sync(~0u, incl, o);
        if (lane >= o) incl += t;
    }
    if (lane == 31) ws[wid] = incl;
    __syncthreads();
    if (tid == 0) {
        int run = 0;
#pragma unroll
        for (int w = 0; w < 4; w++) { int t = ws[w]; ws[w] = run; run += t; }
    }
    __syncthreads();
    int excl = ws[wid] + incl - v;
    if (tid < nblocks) g_bsum[tid] = excl;
}

// Local scan + rowstart/cursor init + dinv (fused)
__global__ __launch_bounds__(256) void k_scan_local(int n, int E) {
    __shared__ int wsum[8];
    int b    = blockIdx.x;
    int base = b * SCAN_BLK + threadIdx.x * 4;
    int lane = threadIdx.x & 31, wid = threadIdx.x >> 5;
    int c[4];
    int t = 0;
#pragma unroll
    for (int i = 0; i < 4; i++) {
        int idx = base + i;
        c[i] = (idx < n) ? g_deg[idx] : 0;
        t += c[i];
    }
    int incl = t;
#pragma unroll
    for (int o = 1; o < 32; o <<= 1) {
        int v = __shfl_up_sync(~0u, incl, o);
        if (lane >= o) incl += v;
    }
    if (lane == 31) wsum[wid] = incl;
    __syncthreads();
    if (threadIdx.x == 0) {
        int run = 0;
#pragma unroll
        for (int w = 0; w < 8; w++) { int v = wsum[w]; wsum[w] = run; run += v; }
    }
    __syncthreads();
    int p = g_bsum[b] + wsum[wid] + incl - t;
#pragma unroll
    for (int i = 0; i < 4; i++) {
        int idx = base + i;
        if (idx < n) {
            g_rowstart[idx] = p;
            g_cursor[idx]   = p;
            g_dinv[idx]     = rsqrtf((float)(c[i] + 1));  // +1 self-loop
        }
        p += c[i];
    }
    if (b == 0 && threadIdx.x == 0) g_rowstart[n] = E;
}

__global__ void k_fill(const int* __restrict__ ei, int E) {
    int e2 = blockIdx.x * blockDim.x + threadIdx.x;   // 2 edges per thread
    int e  = e2 * 2;
    if (e + 1 < E) {
        int2 s = *(const int2*)&ei[e];
        int2 d = *(const int2*)&ei[E + e];
        int p0 = atomicAdd(&g_cursor[d.x], 1);
        g_csr[p0] = s.x;
        int p1 = atomicAdd(&g_cursor[d.y], 1);
        g_csr[p1] = s.y;
    } else if (e < E) {
        int s = ei[e], t = ei[E + e];
        int pos = atomicAdd(&g_cursor[t], 1);
        g_csr[pos] = s;
    }
}

// ---------------------------------------------------------------------------
// GEMM1 (tf32 tensor cores): g_h1h[N,128] = fp16( dinv[row] * (X @ W1) )
// Block 256 threads, tile 128x128, K chunk 32; warp = 32 rows x 64 cols.
// ---------------------------------------------------------------------------
__device__ __forceinline__ unsigned f2tf32(float f) {
    unsigned u;
    asm("cvt.rna.tf32.f32 %0, %1;" : "=r"(u) : "f"(f));
    return u;
}

__global__ __launch_bounds__(256) void k_gemm1(const float* __restrict__ X,
                                               const float* __restrict__ W,
                                               int n) {
    __shared__ unsigned Xs[128 * 36];
    __shared__ unsigned Ws[32 * 136];
    int tid  = threadIdx.x;
    int lane = tid & 31;
    int wid  = tid >> 5;
    int gid  = lane >> 2;
    int tig  = lane & 3;
    int wr   = wid & 3;
    int wc   = wid >> 2;
    int row0 = blockIdx.x * 128;

    float acc[2][8][4];
#pragma unroll
    for (int mt = 0; mt < 2; mt++)
#pragma unroll
        for (int nt = 0; nt < 8; nt++)
#pragma unroll
            for (int q = 0; q < 4; q++) acc[mt][nt][q] = 0.f;

    const float4* X4 = (const float4*)X;
    const float4* W4 = (const float4*)W;

    for (int kt = 0; kt < 4; kt++) {
        __syncthreads();
#pragma unroll
        for (int i = 0; i < 4; i++) {
            int q = tid + i * 256;
            int r = q >> 3, c4 = q & 7;
            int row = row0 + r;
            float4 v = (row < n) ? X4[(size_t)row * 32 + kt * 8 + c4]
                                 : make_float4(0.f, 0.f, 0.f, 0.f);
            unsigned* d = &Xs[r * 36 + c4 * 4];
            d[0] = f2tf32(v.x); d[1] = f2tf32(v.y);
            d[2] = f2tf32(v.z); d[3] = f2tf32(v.w);
        }
#pragma unroll
        for (int i = 0; i < 4; i++) {
            int q = tid + i * 256;
            int r = q >> 5, c4 = q & 31;
            float4 v = W4[(size_t)(kt * 32 + r) * 32 + c4];
            unsigned* d = &Ws[r * 136 + c4 * 4];
            d[0] = f2tf32(v.x); d[1] = f2tf32(v.y);
            d[2] = f2tf32(v.z); d[3] = f2tf32(v.w);
        }
        __syncthreads();

#pragma unroll
        for (int ks = 0; ks < 4; ks++) {
            int kk = ks * 8;
            unsigned a[2][4];
#pragma unroll
            for (int mt = 0; mt < 2; mt++) {
                int rb = wr * 32 + mt * 16;
                a[mt][0] = Xs[(rb + gid) * 36 + kk + tig];
                a[mt][1] = Xs[(rb + gid + 8) * 36 + kk + tig];
                a[mt][2] = Xs[(rb + gid) * 36 + kk + tig + 4];
                a[mt][3] = Xs[(rb + gid + 8) * 36 + kk + tig + 4];
            }
            unsigned b[8][2];
#pragma unroll
            for (int nt = 0; nt < 8; nt++) {
                int col = wc * 64 + nt * 8 + gid;
                b[nt][0] = Ws[(kk + tig) * 136 + col];
                b[nt][1] = Ws[(kk + tig + 4) * 136 + col];
            }
#pragma unroll
            for (int mt = 0; mt < 2; mt++)
#pragma unroll
                for (int nt = 0; nt < 8; nt++) {
                    float* c = acc[mt][nt];
                    asm volatile(
                        "mma.sync.aligned.m16n8k8.row.col.f32.tf32.tf32.f32 "
                        "{%0,%1,%2,%3}, {%4,%5,%6,%7}, {%8,%9}, {%0,%1,%2,%3};"
                        : "+f"(c[0]), "+f"(c[1]), "+f"(c[2]), "+f"(c[3])
                        : "r"(a[mt][0]), "r"(a[mt][1]), "r"(a[mt][2]), "r"(a[mt][3]),
                          "r"(b[nt][0]), "r"(b[nt][1]));
                }
        }
    }

    // Epilogue: scale by dinv, convert to fp16, store half2 per (row, col-pair)
#pragma unroll
    for (int mt = 0; mt < 2; mt++) {
        int rA = row0 + wr * 32 + mt * 16 + gid;
        int rB = rA + 8;
        float dA = (rA < n) ? g_dinv[rA] : 0.f;
        float dB = (rB < n) ? g_dinv[rB] : 0.f;
#pragma unroll
        for (int nt = 0; nt < 8; nt++) {
            int col = wc * 64 + nt * 8 + 2 * tig;
            if (rA < n)
                *(__half2*)&g_h1h[(size_t)rA * 128 + col] =
                    __floats2half2_rn(acc[mt][nt][0] * dA, acc[mt][nt][1] * dA);
            if (rB < n)
                *(__half2*)&g_h1h[(size_t)rB * 128 + col] =
                    __floats2half2_rn(acc[mt][nt][2] * dB, acc[mt][nt][3] * dB);
        }
    }
}

// ---------------------------------------------------------------------------
// Gather layer 1: warp per node; lane owns 4 halves (8B). fp32 accumulate.
// a1[t] = dinv[t] * (h1s[t] + sum_{s in N(t)} h1s[s])
// ---------------------------------------------------------------------------
__global__ __launch_bounds__(256) void k_gather1(int n) {
    int node = blockIdx.x * 8 + (threadIdx.x >> 5);
    int lane = threadIdx.x & 31;
    if (node >= n) return;
    int beg = g_rowstart[node];
    int end = g_rowstart[node + 1];
    const uint2* h8 = (const uint2*)g_h1h;   // 4 halves per element

    uint2  u  = h8[(size_t)node * 32 + lane];  // self-loop term
    float2 f0 = __half22float2(*(__half2*)&u.x);
    float2 f1 = __half22float2(*(__half2*)&u.y);
    float4 acc = make_float4(f0.x, f0.y, f1.x, f1.y);

    int j = beg;
    for (; j + 3 < end; j += 4) {
        int s0 = g_csr[j], s1 = g_csr[j + 1], s2 = g_csr[j + 2], s3 = g_csr[j + 3];
        uint2 a = h8[(size_t)s0 * 32 + lane];
        uint2 b = h8[(size_t)s1 * 32 + lane];
        uint2 c = h8[(size_t)s2 * 32 + lane];
        uint2 d = h8[(size_t)s3 * 32 + lane];
        float2 a0 = __half22float2(*(__half2*)&a.x), a1 = __half22float2(*(__half2*)&a.y);
        float2 b0 = __half22float2(*(__half2*)&b.x), b1 = __half22float2(*(__half2*)&b.y);
        float2 c0 = __half22float2(*(__half2*)&c.x), c1 = __half22float2(*(__half2*)&c.y);
        float2 d0 = __half22float2(*(__half2*)&d.x), d1 = __half22float2(*(__half2*)&d.y);
        acc.x += (a0.x + b0.x) + (c0.x + d0.x);
        acc.y += (a0.y + b0.y) + (c0.y + d0.y);
        acc.z += (a1.x + b1.x) + (c1.x + d1.x);
        acc.w += (a1.y + b1.y) + (c1.y + d1.y);
    }
    for (; j < end; j++) {
        uint2 a = h8[(size_t)g_csr[j] * 32 + lane];
        float2 a0 = __half22float2(*(__half2*)&a.x), a1 = __half22float2(*(__half2*)&a.y);
        acc.x += a0.x; acc.y += a0.y; acc.z += a1.x; acc.w += a1.y;
    }
    float d = g_dinv[node];
    acc.x *= d; acc.y *= d; acc.z *= d; acc.w *= d;
    ((float4*)g_a1)[(size_t)node * 32 + lane] = acc;
}

// ---------------------------------------------------------------------------
// GEMM2: g_h2h[N,16] = fp16( dinv * (relu(g_a1 + b1) @ W2) )
// 256 threads, 256-row tile, thread = 4 rows x 4 cols, K chunk 32.
// ---------------------------------------------------------------------------
__global__ __launch_bounds__(256) void k_gemm2(const float* __restrict__ b1,
                                               const float* __restrict__ W2,
                                               int n) {
    __shared__ float As[256 * 33];
    __shared__ float W2s[128 * 16];
    __shared__ float b1s[128];
    int tid  = threadIdx.x;
    int cgrp = tid & 3;
    int tg   = tid >> 2;
    int row0 = blockIdx.x * 256;

    if (tid < 128) b1s[tid] = b1[tid];
#pragma unroll
    for (int i = 0; i < 8; i++) W2s[tid + i * 256] = W2[tid + i * 256];

    float4 acc[4];
#pragma unroll
    for (int i = 0; i < 4; i++) acc[i] = make_float4(0.f, 0.f, 0.f, 0.f);

    for (int kc = 0; kc < 4; kc++) {
        __syncthreads();
#pragma unroll
        for (int i = 0; i < 8; i++) {
            int q = tid + i * 256;
            int r = q >> 3, c4 = q & 7;
            int row = row0 + r;
            float4 v = make_float4(0.f, 0.f, 0.f, 0.f);
            if (row < n) {
                float4 a = ((const float4*)g_a1)[(size_t)row * 32 + kc * 8 + c4];
                const float* bb = &b1s[kc * 32 + c4 * 4];
                v.x = fmaxf(a.x + bb[0], 0.f);
                v.y = fmaxf(a.y + bb[1], 0.f);
                v.z = fmaxf(a.z + bb[2], 0.f);
                v.w = fmaxf(a.w + bb[3], 0.f);
            }
            float* d = &As[r * 33 + c4 * 4];
            d[0] = v.x; d[1] = v.y; d[2] = v.z; d[3] = v.w;
        }
        __syncthreads();

#pragma unroll 8
        for (int kk = 0; kk < 32; kk++) {
            float4 w = *(const float4*)&W2s[(kc * 32 + kk) * 16 + cgrp * 4];
#pragma unroll
            for (int i = 0; i < 4; i++) {
                float xv = As[(tg * 4 + i) * 33 + kk];
                acc[i].x = fmaf(xv, w.x, acc[i].x);
                acc[i].y = fmaf(xv, w.y, acc[i].y);
                acc[i].z = fmaf(xv, w.z, acc[i].z);
                acc[i].w = fmaf(xv, w.w, acc[i].w);
            }
        }
    }

#pragma unroll
    for (int i = 0; i < 4; i++) {
        int row = row0 + tg * 4 + i;
        if (row < n) {
            float d = g_dinv[row];
            __half2 lo = __floats2half2_rn(acc[i].x * d, acc[i].y * d);
            __half2 hi = __floats2half2_rn(acc[i].z * d, acc[i].w * d);
            uint2 pk;
            pk.x = *(unsigned*)&lo;
            pk.y = *(unsigned*)&hi;
            *(uint2*)&g_h2h[(size_t)row * 16 + cgrp * 4] = pk;
        }
    }
}

// ---------------------------------------------------------------------------
// Gather layer 2: 4 threads/node, each owns 4 halves (8B); out fp32 (+b2).
// ---------------------------------------------------------------------------
__global__ __launch_bounds__(256) void k_gather2(const float* __restrict__ b2,
                                                 float* __restrict__ out, int n) {
    int gid  = blockIdx.x * 256 + threadIdx.x;
    int node = gid >> 2;
    int j4   = gid & 3;
    if (node >= n) return;
    int beg = g_rowstart[node];
    int end = g_rowstart[node + 1];
    const uint2* h8 = (const uint2*)g_h2h;

    uint2  u  = h8[(size_t)node * 4 + j4];
    float2 f0 = __half22float2(*(__half2*)&u.x);
    float2 f1 = __half22float2(*(__half2*)&u.y);
    float4 acc = make_float4(f0.x, f0.y, f1.x, f1.y);

    int j = beg;
    for (; j + 1 < end; j += 2) {
        uint2 a = h8[(size_t)g_csr[j] * 4 + j4];
        uint2 b = h8[(size_t)g_csr[j + 1] * 4 + j4];
        float2 a0 = __half22float2(*(__half2*)&a.x), a1 = __half22float2(*(__half2*)&a.y);
        float2 b0 = __half22float2(*(__half2*)&b.x), b1 = __half22float2(*(__half2*)&b.y);
        acc.x += a0.x + b0.x;
        acc.y += a0.y + b0.y;
        acc.z += a1.x + b1.x;
        acc.w += a1.y + b1.y;
    }
    if (j < end) {
        uint2 a = h8[(size_t)g_csr[j] * 4 + j4];
        float2 a0 = __half22float2(*(__half2*)&a.x), a1 = __half22float2(*(__half2*)&a.y);
        acc.x += a0.x; acc.y += a0.y; acc.z += a1.x; acc.w += a1.y;
    }
    float  d  = g_dinv[node];
    float4 bb = ((const float4*)b2)[j4];
    acc.x = fmaf(acc.x, d, bb.x);
    acc.y = fmaf(acc.y, d, bb.y);
    acc.z = fmaf(acc.z, d, bb.z);
    acc.w = fmaf(acc.w, d, bb.w);
    ((float4*)out)[(size_t)node * 4 + j4] = acc;
}

// ---------------------------------------------------------------------------
extern "C" void kernel_launch(void* const* d_in, const int* in_sizes, int n_in,
                              void* d_out, int out_size) {
    const float* x   = (const float*)d_in[0];
    const int*   ei  = (const int*)d_in[1];   // int32 [2, E]
    const float* W1  = (const float*)d_in[2];
    const float* b1  = (const float*)d_in[3];
    const float* W2  = (const float*)d_in[4];
    const float* b2  = (const float*)d_in[5];
    float*       out = (float*)d_out;

    int n = in_sizes[0] / DIN;   // 100000
    int E = in_sizes[1] / 2;     // 1600000
    int nblocks = (n + SCAN_BLK - 1) / SCAN_BLK;  // 98

    // degree + CSR build
    k_deg_zero   <<<(n + 255) / 256, 256>>>(n);
    k_deg_count  <<<(E / 2 + 256) / 256, 256>>>(ei, E);
    k_scan_reduce<<<nblocks, 256>>>(n);
    k_scan_top   <<<1, 128>>>(nblocks);
    k_scan_local <<<nblocks, 256>>>(n, E);
    k_fill       <<<(E / 2 + 256) / 256, 256>>>(ei, E);

    // layer 1
    k_gemm1  <<<(n + 127) / 128, 256>>>(x, W1, n);
    k_gather1<<<(n + 7) / 8, 256>>>(n);

    // layer 2
    k_gemm2  <<<(n + 255) / 256, 256>>>(b1, W2, n);
    k_gather2<<<(n * 4 + 255) / 256, 256>>>(b2, out, n);
}